// round 1
// baseline (speedup 1.0000x reference)
#include <cuda_runtime.h>
#include <cuda_bf16.h>
#include <cstdint>

// GRU cell, B=8192, I=H=1024, fp32 in/out.
// Two fused GEMM kernels using mma.sync tf32 (m16n8k8), cp.async double buffering.
//   K1: z = sigmoid(x Wwz^T + h Wuz^T); rh = sigmoid(x Wwr^T + h Wur^T) * h
//   K2: out = z*h + (1-z)*tanh(rh Wu^T + x Ww^T)

#define BB 8192
#define HH 1024
#define KK 1024

// scratch (allocation-free rule: __device__ globals)
__device__ float g_Z[BB * HH];
__device__ float g_RH[BB * HH];

// tiles
#define BM 128
#define BN 64
#define BK 32
#define NTHREADS 256
#define STRIDE 36                 // padded smem row stride in floats (bank-conflict-free, 16B aligned)
#define A_TILE (BM * STRIDE)      // 4608 floats
#define B_TILE (BN * STRIDE)      // 2304 floats

__device__ __forceinline__ void cp_async16(float* sdst, const float* gsrc) {
    uint32_t s = (uint32_t)__cvta_generic_to_shared(sdst);
    asm volatile("cp.async.cg.shared.global [%0], [%1], 16;\n" :: "r"(s), "l"(gsrc));
}
__device__ __forceinline__ void cp_commit() { asm volatile("cp.async.commit_group;\n"); }
__device__ __forceinline__ void cp_wait_all() { asm volatile("cp.async.wait_group 0;\n"); }

__device__ __forceinline__ uint32_t f2tf(float f) {
    uint32_t u;
    asm("cvt.rna.tf32.f32 %0, %1;" : "=r"(u) : "f"(f));
    return u;
}

__device__ __forceinline__ void mma_tf32(float c[4], const uint32_t a[4], uint32_t b0, uint32_t b1) {
    asm volatile(
        "mma.sync.aligned.m16n8k8.row.col.f32.tf32.tf32.f32 "
        "{%0,%1,%2,%3},{%4,%5,%6,%7},{%8,%9},{%0,%1,%2,%3};\n"
        : "+f"(c[0]), "+f"(c[1]), "+f"(c[2]), "+f"(c[3])
        : "r"(a[0]), "r"(a[1]), "r"(a[2]), "r"(a[3]), "r"(b0), "r"(b1));
}

__device__ __forceinline__ float sigmoidf_(float v) { return 1.0f / (1.0f + expf(-v)); }

// ---------------------------------------------------------------------------
// Kernel 1: dual-accumulator GEMM (z_pre, r_pre), epilogue -> g_Z, g_RH
// ---------------------------------------------------------------------------
__global__ void __launch_bounds__(NTHREADS, 2)
gemm_zr(const float* __restrict__ x, const float* __restrict__ h,
        const float* __restrict__ Wwz, const float* __restrict__ Wuz,
        const float* __restrict__ Wwr, const float* __restrict__ Wur) {
    extern __shared__ float smem[];
    float* As = smem;                    // 2 * A_TILE
    float* Bz = smem + 2 * A_TILE;       // 2 * B_TILE
    float* Br = Bz + 2 * B_TILE;         // 2 * B_TILE

    const int tid = threadIdx.x;
    const int wid = tid >> 5;
    const int lane = tid & 31;
    const int g = lane >> 2;             // groupID 0..7
    const int tq = lane & 3;             // thread-in-group 0..3
    const int wm = (wid & 3) * 32;       // warp row offset within tile
    const int wn = (wid >> 2) * 32;      // warp col offset within tile
    const int bm = blockIdx.x * BM;
    const int bn = blockIdx.y * BN;

    auto stage = [&](int t, int buf) {
        const int seg = t >> 5;               // 0: x-side, 1: h-side
        const int k0 = (t & 31) << 5;         // k offset within 1024
        const float* A  = seg ? h   : x;
        const float* Ba = seg ? Wuz : Wwz;
        const float* Bb = seg ? Wur : Wwr;
        #pragma unroll
        for (int i = 0; i < 4; i++) {
            int slot = tid + i * NTHREADS;    // 1024 slots of 16B
            int r = slot >> 3, c = (slot & 7) << 2;
            cp_async16(&As[buf * A_TILE + r * STRIDE + c], &A[(bm + r) * KK + k0 + c]);
        }
        #pragma unroll
        for (int i = 0; i < 2; i++) {
            int slot = tid + i * NTHREADS;    // 512 slots
            int r = slot >> 3, c = (slot & 7) << 2;
            cp_async16(&Bz[buf * B_TILE + r * STRIDE + c], &Ba[(bn + r) * KK + k0 + c]);
            cp_async16(&Br[buf * B_TILE + r * STRIDE + c], &Bb[(bn + r) * KK + k0 + c]);
        }
        cp_commit();
    };

    float accZ[2][4][4];
    float accR[2][4][4];
    #pragma unroll
    for (int mt = 0; mt < 2; mt++)
        #pragma unroll
        for (int nt = 0; nt < 4; nt++)
            #pragma unroll
            for (int i = 0; i < 4; i++) { accZ[mt][nt][i] = 0.f; accR[mt][nt][i] = 0.f; }

    stage(0, 0);

    const int NT = 64;                        // 2 segments * 32 k-chunks
    for (int t = 0; t < NT; t++) {
        cp_wait_all();
        __syncthreads();
        if (t + 1 < NT) stage(t + 1, (t + 1) & 1);

        const int buf = t & 1;
        const float* Ab  = &As[buf * A_TILE];
        const float* Bzb = &Bz[buf * B_TILE];
        const float* Brb = &Br[buf * B_TILE];

        #pragma unroll
        for (int kk = 0; kk < 4; kk++) {
            uint32_t a[2][4];
            #pragma unroll
            for (int mt = 0; mt < 2; mt++) {
                int r0 = wm + mt * 16 + g;
                a[mt][0] = f2tf(Ab[(r0    ) * STRIDE + kk * 8 + tq    ]);
                a[mt][1] = f2tf(Ab[(r0 + 8) * STRIDE + kk * 8 + tq    ]);
                a[mt][2] = f2tf(Ab[(r0    ) * STRIDE + kk * 8 + tq + 4]);
                a[mt][3] = f2tf(Ab[(r0 + 8) * STRIDE + kk * 8 + tq + 4]);
            }
            #pragma unroll
            for (int nt = 0; nt < 4; nt++) {
                int n0 = wn + nt * 8 + g;
                uint32_t bz0 = f2tf(Bzb[n0 * STRIDE + kk * 8 + tq    ]);
                uint32_t bz1 = f2tf(Bzb[n0 * STRIDE + kk * 8 + tq + 4]);
                uint32_t br0 = f2tf(Brb[n0 * STRIDE + kk * 8 + tq    ]);
                uint32_t br1 = f2tf(Brb[n0 * STRIDE + kk * 8 + tq + 4]);
                #pragma unroll
                for (int mt = 0; mt < 2; mt++) {
                    mma_tf32(accZ[mt][nt], a[mt], bz0, bz1);
                    mma_tf32(accR[mt][nt], a[mt], br0, br1);
                }
            }
        }
        __syncthreads();
    }

    // epilogue: z = sigmoid(z_pre), rh = sigmoid(r_pre) * h
    #pragma unroll
    for (int mt = 0; mt < 2; mt++)
        #pragma unroll
        for (int nt = 0; nt < 4; nt++)
            #pragma unroll
            for (int i = 0; i < 4; i++) {
                int row = bm + wm + mt * 16 + g + ((i >> 1) << 3);
                int col = bn + wn + nt * 8 + tq * 2 + (i & 1);
                int idx = row * HH + col;
                float hv = h[idx];
                float zv = sigmoidf_(accZ[mt][nt][i]);
                float rv = sigmoidf_(accR[mt][nt][i]);
                g_Z[idx] = zv;
                g_RH[idx] = rv * hv;
            }
}

// ---------------------------------------------------------------------------
// Kernel 2: u = rh Wu^T + x Ww^T ; out = z*h + (1-z)*tanh(u)
// ---------------------------------------------------------------------------
__global__ void __launch_bounds__(NTHREADS, 2)
gemm_ht(const float* __restrict__ x, const float* __restrict__ h,
        const float* __restrict__ Wu, const float* __restrict__ Ww,
        float* __restrict__ out) {
    extern __shared__ float smem[];
    float* As = smem;                  // 2 * A_TILE
    float* Bs = smem + 2 * A_TILE;     // 2 * B_TILE

    const int tid = threadIdx.x;
    const int wid = tid >> 5;
    const int lane = tid & 31;
    const int g = lane >> 2;
    const int tq = lane & 3;
    const int wm = (wid & 3) * 32;
    const int wn = (wid >> 2) * 32;
    const int bm = blockIdx.x * BM;
    const int bn = blockIdx.y * BN;

    auto stage = [&](int t, int buf) {
        const int seg = t >> 5;
        const int k0 = (t & 31) << 5;
        const float* A = seg ? x  : (const float*)g_RH;
        const float* Bp = seg ? Ww : Wu;
        #pragma unroll
        for (int i = 0; i < 4; i++) {
            int slot = tid + i * NTHREADS;
            int r = slot >> 3, c = (slot & 7) << 2;
            cp_async16(&As[buf * A_TILE + r * STRIDE + c], &A[(bm + r) * KK + k0 + c]);
        }
        #pragma unroll
        for (int i = 0; i < 2; i++) {
            int slot = tid + i * NTHREADS;
            int r = slot >> 3, c = (slot & 7) << 2;
            cp_async16(&Bs[buf * B_TILE + r * STRIDE + c], &Bp[(bn + r) * KK + k0 + c]);
        }
        cp_commit();
    };

    float acc[2][4][4];
    #pragma unroll
    for (int mt = 0; mt < 2; mt++)
        #pragma unroll
        for (int nt = 0; nt < 4; nt++)
            #pragma unroll
            for (int i = 0; i < 4; i++) acc[mt][nt][i] = 0.f;

    stage(0, 0);

    const int NT = 64;
    for (int t = 0; t < NT; t++) {
        cp_wait_all();
        __syncthreads();
        if (t + 1 < NT) stage(t + 1, (t + 1) & 1);

        const int buf = t & 1;
        const float* Ab = &As[buf * A_TILE];
        const float* Bb = &Bs[buf * B_TILE];

        #pragma unroll
        for (int kk = 0; kk < 4; kk++) {
            uint32_t a[2][4];
            #pragma unroll
            for (int mt = 0; mt < 2; mt++) {
                int r0 = wm + mt * 16 + g;
                a[mt][0] = f2tf(Ab[(r0    ) * STRIDE + kk * 8 + tq    ]);
                a[mt][1] = f2tf(Ab[(r0 + 8) * STRIDE + kk * 8 + tq    ]);
                a[mt][2] = f2tf(Ab[(r0    ) * STRIDE + kk * 8 + tq + 4]);
                a[mt][3] = f2tf(Ab[(r0 + 8) * STRIDE + kk * 8 + tq + 4]);
            }
            #pragma unroll
            for (int nt = 0; nt < 4; nt++) {
                int n0 = wn + nt * 8 + g;
                uint32_t b0 = f2tf(Bb[n0 * STRIDE + kk * 8 + tq    ]);
                uint32_t b1 = f2tf(Bb[n0 * STRIDE + kk * 8 + tq + 4]);
                #pragma unroll
                for (int mt = 0; mt < 2; mt++)
                    mma_tf32(acc[mt][nt], a[mt], b0, b1);
            }
        }
        __syncthreads();
    }

    // epilogue: out = z*h + (1-z)*tanh(u)
    #pragma unroll
    for (int mt = 0; mt < 2; mt++)
        #pragma unroll
        for (int nt = 0; nt < 4; nt++)
            #pragma unroll
            for (int i = 0; i < 4; i++) {
                int row = bm + wm + mt * 16 + g + ((i >> 1) << 3);
                int col = bn + wn + nt * 8 + tq * 2 + (i & 1);
                int idx = row * HH + col;
                float zv = g_Z[idx];
                float hv = h[idx];
                float ht = tanhf(acc[mt][nt][i]);
                out[idx] = zv * hv + (1.0f - zv) * ht;
            }
}

// ---------------------------------------------------------------------------
extern "C" void kernel_launch(void* const* d_in, const int* in_sizes, int n_in,
                              void* d_out, int out_size) {
    const float* x   = (const float*)d_in[0];
    const float* h   = (const float*)d_in[1];
    const float* Wwz = (const float*)d_in[2];
    const float* Wuz = (const float*)d_in[3];
    const float* Wwr = (const float*)d_in[4];
    const float* Wur = (const float*)d_in[5];
    const float* Wu  = (const float*)d_in[6];
    const float* Ww  = (const float*)d_in[7];
    float* out = (float*)d_out;

    const int smem1 = (2 * A_TILE + 4 * B_TILE) * 4;   // 73728 B
    const int smem2 = (2 * A_TILE + 2 * B_TILE) * 4;   // 55296 B
    cudaFuncSetAttribute(gemm_zr, cudaFuncAttributeMaxDynamicSharedMemorySize, smem1);
    cudaFuncSetAttribute(gemm_ht, cudaFuncAttributeMaxDynamicSharedMemorySize, smem2);

    dim3 grid(BB / BM, HH / BN);   // 64 x 16
    dim3 blk(NTHREADS);
    gemm_zr<<<grid, blk, smem1>>>(x, h, Wwz, Wuz, Wwr, Wur);
    gemm_ht<<<grid, blk, smem2>>>(x, h, Wu, Ww, out);
}

// round 3
// speedup vs baseline: 1.2571x; 1.2571x over previous
#include <cuda_runtime.h>
#include <cstdint>

// GRU cell B=8192, I=H=1024 fp32. mma.sync tf32 with pre-rounded, pre-permuted
// operands (fragment-ordered layouts) so the mainloop is HMMA + wide LDS only.
//   prep:   round-to-tf32 + permute x,h -> g_xp,g_hp ; 6 weights -> g_Wp[]
//   zr:     z = sigmoid(x Wwz^T + h Wuz^T); rh = sigmoid(x Wwr^T + h Wur^T)*h
//           (z linear, rh written rounded+permuted)
//   ht:     out = z*h + (1-z)*tanh(rh Wu^T + x Ww^T)

#define BB 8192
#define HH 1024
#define KK 1024

// Permuted layouts:
//  A_perm[rb][kb][lane][4] : rb=row/16, kb=k/8, lane=g*4+tq (g=lane>>2,tq=lane&3)
//     [0]=A[16rb+g][8kb+tq] [1]=A[16rb+8+g][8kb+tq] [2]=A[16rb+g][8kb+tq+4] [3]=A[16rb+8+g][8kb+tq+4]
//  B_perm[nb][kb][lane][2] : nb=n/8
//     [0]=W[8nb+g][8kb+tq]  [1]=W[8nb+g][8kb+tq+4]
__device__ __align__(16) float g_xp[BB * KK];
__device__ __align__(16) float g_hp[BB * KK];
__device__ __align__(16) float g_rhp[BB * KK];
__device__ __align__(16) float g_Z[BB * HH];
__device__ __align__(16) float g_Wp[6][HH * KK];  // 0:Wwz 1:Wuz 2:Wwr 3:Wur 4:Wu 5:Ww

__device__ __forceinline__ float rndtf(float f) {
    uint32_t u;
    asm("cvt.rna.tf32.f32 %0, %1;" : "=r"(u) : "f"(f));
    return __uint_as_float(u);
}
__device__ __forceinline__ void cp_async16(float* sdst, const void* gsrc) {
    uint32_t s = (uint32_t)__cvta_generic_to_shared(sdst);
    asm volatile("cp.async.cg.shared.global [%0], [%1], 16;\n" :: "r"(s), "l"(gsrc));
}
__device__ __forceinline__ void cp_commit() { asm volatile("cp.async.commit_group;\n"); }
__device__ __forceinline__ void cp_wait_all() { asm volatile("cp.async.wait_group 0;\n"); }

__device__ __forceinline__ void mma8(float c[4], const uint4& a, const uint2& b) {
    asm volatile(
        "mma.sync.aligned.m16n8k8.row.col.f32.tf32.tf32.f32 "
        "{%0,%1,%2,%3},{%4,%5,%6,%7},{%8,%9},{%0,%1,%2,%3};\n"
        : "+f"(c[0]), "+f"(c[1]), "+f"(c[2]), "+f"(c[3])
        : "r"(a.x), "r"(a.y), "r"(a.z), "r"(a.w), "r"(b.x), "r"(b.y));
}
__device__ __forceinline__ float sig_(float v) { return 1.0f / (1.0f + __expf(-v)); }

// ---------------------------------------------------------------------------
// Preprocess: round + permute
// ---------------------------------------------------------------------------
__global__ void __launch_bounds__(256) permA(const float* __restrict__ x,
                                             const float* __restrict__ hm) {
    const float* src = blockIdx.y ? hm : x;
    float* dst = blockIdx.y ? g_hp : g_xp;
    int t = blockIdx.x * 256 + threadIdx.x;      // 0..2M-1
    int lane = t & 31, kb = (t >> 5) & 127, rb = t >> 12;
    int g = lane >> 2, tq = lane & 3;
    const float* s = src + (rb * 16 + g) * KK + kb * 8 + tq;
    float4 v;
    v.x = rndtf(s[0]);
    v.y = rndtf(s[8 * KK]);
    v.z = rndtf(s[4]);
    v.w = rndtf(s[8 * KK + 4]);
    reinterpret_cast<float4*>(dst)[t] = v;
}

__global__ void __launch_bounds__(256) permB(
    const float* __restrict__ w0, const float* __restrict__ w1,
    const float* __restrict__ w2, const float* __restrict__ w3,
    const float* __restrict__ w4, const float* __restrict__ w5) {
    const float* srcs[6] = {w0, w1, w2, w3, w4, w5};
    const float* src = srcs[blockIdx.y];
    float* dst = g_Wp[blockIdx.y];
    int t = blockIdx.x * 256 + threadIdx.x;      // 0..512K-1
    int lane = t & 31, kb = (t >> 5) & 127, nb = t >> 12;
    int g = lane >> 2, tq = lane & 3;
    const float* s = src + (nb * 8 + g) * KK + kb * 8 + tq;
    float2 v;
    v.x = rndtf(s[0]);
    v.y = rndtf(s[4]);
    reinterpret_cast<float2*>(dst)[t] = v;
}

// ---------------------------------------------------------------------------
// Kernel 1: dual-accumulator z/r GEMM. Tile 128x64, 8 warps of 32x32.
// smem floats: A: buf*4096 ; Bz: 8192+buf*2048 ; Br: 12288+buf*2048  (64KB)
// ---------------------------------------------------------------------------
__global__ void __launch_bounds__(256, 2) gemm_zr(const float* __restrict__ h) {
    extern __shared__ float sm[];
    const int tid = threadIdx.x, wid = tid >> 5, lane = tid & 31;
    const int g = lane >> 2, tq = lane & 3;
    const int bm = blockIdx.x * 128, bn = blockIdx.y * 64;
    const int rb0 = bm >> 4, nb0 = bn >> 3;

    auto stage = [&](int t, int buf) {
        const int seg = t >> 5, kbt = t & 31;
        const float4* Ag = reinterpret_cast<const float4*>(seg ? g_hp : g_xp);
        const float4* Bz = reinterpret_cast<const float4*>(g_Wp[seg ? 1 : 0]);
        const float4* Br = reinterpret_cast<const float4*>(g_Wp[seg ? 3 : 2]);
        #pragma unroll
        for (int i = 0; i < 4; i++) {
            int c = tid + i * 256, r = c >> 7, rem = c & 127;
            cp_async16(&sm[buf * 4096 + (r * 128 + rem) * 4],
                       &Ag[(rb0 + r) * 4096 + kbt * 128 + rem]);
        }
        #pragma unroll
        for (int i = 0; i < 2; i++) {
            int c = tid + i * 256, nb = c >> 6, rem = c & 63;
            int go = (nb0 + nb) * 2048 + kbt * 64 + rem;
            cp_async16(&sm[8192 + buf * 2048 + (nb * 64 + rem) * 4], &Bz[go]);
            cp_async16(&sm[12288 + buf * 2048 + (nb * 64 + rem) * 4], &Br[go]);
        }
        cp_commit();
    };

    float accZ[2][4][4] = {}, accR[2][4][4] = {};
    stage(0, 0);

    const int r0 = (wid & 3) * 2, nbl = (wid >> 2) * 4;
    for (int t = 0; t < 64; t++) {
        cp_wait_all();
        __syncthreads();
        if (t + 1 < 64) stage(t + 1, (t + 1) & 1);
        const int buf = t & 1;
        const float* A_ = &sm[buf * 4096];
        const float* Bz_ = &sm[8192 + buf * 2048];
        const float* Br_ = &sm[12288 + buf * 2048];
        #pragma unroll
        for (int kk = 0; kk < 4; kk++) {
            uint4 a0 = *reinterpret_cast<const uint4*>(&A_[(r0 * 4 + kk) * 128 + lane * 4]);
            uint4 a1 = *reinterpret_cast<const uint4*>(&A_[((r0 + 1) * 4 + kk) * 128 + lane * 4]);
            #pragma unroll
            for (int nt = 0; nt < 4; nt++) {
                uint2 bz = *reinterpret_cast<const uint2*>(&Bz_[((nbl + nt) * 4 + kk) * 64 + lane * 2]);
                uint2 br = *reinterpret_cast<const uint2*>(&Br_[((nbl + nt) * 4 + kk) * 64 + lane * 2]);
                mma8(accZ[0][nt], a0, bz);
                mma8(accZ[1][nt], a1, bz);
                mma8(accR[0][nt], a0, br);
                mma8(accR[1][nt], a1, br);
            }
        }
        __syncthreads();
    }

    // epilogue: z linear (float2), rh rounded + permuted (scalar)
    const int wm = (wid & 3) * 32, wn = (wid >> 2) * 32;
    #pragma unroll
    for (int mt = 0; mt < 2; mt++) {
        const int rowb = bm + wm + mt * 16 + g;
        const int rb = (bm + wm + mt * 16) >> 4;
        #pragma unroll
        for (int nt = 0; nt < 4; nt++) {
            const int colb = bn + wn + nt * 8 + tq * 2;
            const int kb = (bn + wn + nt * 8) >> 3;
            #pragma unroll
            for (int half = 0; half < 2; half++) {
                const int row = rowb + half * 8;
                const int idx = row * HH + colb;
                float2 hv = *reinterpret_cast<const float2*>(&h[idx]);
                float z0 = sig_(accZ[mt][nt][half * 2]);
                float z1 = sig_(accZ[mt][nt][half * 2 + 1]);
                float rh0 = sig_(accR[mt][nt][half * 2]) * hv.x;
                float rh1 = sig_(accR[mt][nt][half * 2 + 1]) * hv.y;
                float2 zo = {z0, z1};
                *reinterpret_cast<float2*>(&g_Z[idx]) = zo;
                #pragma unroll
                for (int e = 0; e < 2; e++) {
                    int cin = tq * 2 + e;
                    int tqp = cin & 3, khi = cin >> 2;
                    int lanep = g * 4 + tqp;
                    int j = half + 2 * khi;
                    g_rhp[((rb * 128 + kb) * 32 + lanep) * 4 + j] = rndtf(e ? rh1 : rh0);
                }
            }
        }
    }
}

// ---------------------------------------------------------------------------
// Kernel 2: u = rh Wu^T + x Ww^T ; out = z*h + (1-z)*tanh(u)
// smem floats: A: buf*4096 ; B: 8192+buf*2048  (48KB)
// ---------------------------------------------------------------------------
__global__ void __launch_bounds__(256, 2) gemm_ht(const float* __restrict__ h,
                                                  float* __restrict__ out) {
    extern __shared__ float sm[];
    const int tid = threadIdx.x, wid = tid >> 5, lane = tid & 31;
    const int g = lane >> 2, tq = lane & 3;
    const int bm = blockIdx.x * 128, bn = blockIdx.y * 64;
    const int rb0 = bm >> 4, nb0 = bn >> 3;

    auto stage = [&](int t, int buf) {
        const int seg = t >> 5, kbt = t & 31;
        const float4* Ag = reinterpret_cast<const float4*>(seg ? g_xp : g_rhp);
        const float4* Bg = reinterpret_cast<const float4*>(g_Wp[seg ? 5 : 4]);
        #pragma unroll
        for (int i = 0; i < 4; i++) {
            int c = tid + i * 256, r = c >> 7, rem = c & 127;
            cp_async16(&sm[buf * 4096 + (r * 128 + rem) * 4],
                       &Ag[(rb0 + r) * 4096 + kbt * 128 + rem]);
        }
        #pragma unroll
        for (int i = 0; i < 2; i++) {
            int c = tid + i * 256, nb = c >> 6, rem = c & 63;
            cp_async16(&sm[8192 + buf * 2048 + (nb * 64 + rem) * 4],
                       &Bg[(nb0 + nb) * 2048 + kbt * 64 + rem]);
        }
        cp_commit();
    };

    float acc[2][4][4] = {};
    stage(0, 0);

    const int r0 = (wid & 3) * 2, nbl = (wid >> 2) * 4;
    for (int t = 0; t < 64; t++) {
        cp_wait_all();
        __syncthreads();
        if (t + 1 < 64) stage(t + 1, (t + 1) & 1);
        const int buf = t & 1;
        const float* A_ = &sm[buf * 4096];
        const float* B_ = &sm[8192 + buf * 2048];
        #pragma unroll
        for (int kk = 0; kk < 4; kk++) {
            uint4 a0 = *reinterpret_cast<const uint4*>(&A_[(r0 * 4 + kk) * 128 + lane * 4]);
            uint4 a1 = *reinterpret_cast<const uint4*>(&A_[((r0 + 1) * 4 + kk) * 128 + lane * 4]);
            #pragma unroll
            for (int nt = 0; nt < 4; nt++) {
                uint2 b = *reinterpret_cast<const uint2*>(&B_[((nbl + nt) * 4 + kk) * 64 + lane * 2]);
                mma8(acc[0][nt], a0, b);
                mma8(acc[1][nt], a1, b);
            }
        }
        __syncthreads();
    }

    const int wm = (wid & 3) * 32, wn = (wid >> 2) * 32;
    #pragma unroll
    for (int mt = 0; mt < 2; mt++) {
        const int rowb = bm + wm + mt * 16 + g;
        #pragma unroll
        for (int nt = 0; nt < 4; nt++) {
            const int colb = bn + wn + nt * 8 + tq * 2;
            #pragma unroll
            for (int half = 0; half < 2; half++) {
                const int idx = (rowb + half * 8) * HH + colb;
                float2 hv = *reinterpret_cast<const float2*>(&h[idx]);
                float2 zv = *reinterpret_cast<const float2*>(&g_Z[idx]);
                float2 ov;
                ov.x = zv.x * hv.x + (1.0f - zv.x) * tanhf(acc[mt][nt][half * 2]);
                ov.y = zv.y * hv.y + (1.0f - zv.y) * tanhf(acc[mt][nt][half * 2 + 1]);
                *reinterpret_cast<float2*>(&out[idx]) = ov;
            }
        }
    }
}

// ---------------------------------------------------------------------------
extern "C" void kernel_launch(void* const* d_in, const int* in_sizes, int n_in,
                              void* d_out, int out_size) {
    const float* x   = (const float*)d_in[0];
    const float* h   = (const float*)d_in[1];
    const float* Wwz = (const float*)d_in[2];
    const float* Wuz = (const float*)d_in[3];
    const float* Wwr = (const float*)d_in[4];
    const float* Wur = (const float*)d_in[5];
    const float* Wu  = (const float*)d_in[6];
    const float* Ww  = (const float*)d_in[7];
    float* out = (float*)d_out;

    const int s1 = 16384 * 4;   // 64 KB
    const int s2 = 12288 * 4;   // 48 KB
    cudaFuncSetAttribute(gemm_zr, cudaFuncAttributeMaxDynamicSharedMemorySize, s1);
    cudaFuncSetAttribute(gemm_ht, cudaFuncAttributeMaxDynamicSharedMemorySize, s2);

    permA<<<dim3(8192, 2), 256>>>(x, h);
    permB<<<dim3(2048, 6), 256>>>(Wwz, Wuz, Wwr, Wur, Wu, Ww);
    gemm_zr<<<dim3(64, 16), 256, s1>>>(h);
    gemm_ht<<<dim3(64, 16), 256, s2>>>(h, out);
}

// round 4
// speedup vs baseline: 2.3351x; 1.8575x over previous
#include <cuda_runtime.h>
#include <cuda_fp16.h>
#include <cstdint>

// GRU cell B=8192, I=H=1024 fp32. mma.sync fp16 (m16n8k16, fp32 accum) with
// pre-converted, fragment-permuted operands. fp16 mantissa == tf32 mantissa,
// so accuracy matches the tf32 version (rel_err ~1.6e-4) at 2x tensor rate
// and half the smem/DRAM operand traffic.
//   prep:  fp16+permute x,h -> g_xp,g_hp ; 6 weights -> g_Wh[]
//   zr:    z=sigmoid(x Wwz^T + h Wuz^T) -> g_Z (f32)
//          rh=sigmoid(x Wwr^T + h Wur^T)*h -> g_rhp (fp16, fragment order)
//   ht:    out = z*h + (1-z)*tanh(rh Wu^T + x Ww^T)

#define BB 8192
#define HH 1024
#define KK 1024

// A fragment layout (m16n8k16, row-major A 16x16 block):
//  g_ap[((rb*64+kb)*32+lane)] = uint4{a0,a1,a2,a3}, lane=g*4+tq
//   a0={A[16rb+g][16kb+tq*2],+1} a1={A[16rb+8+g][...]}
//   a2={A[16rb+g][16kb+8+tq*2],+1} a3={A[16rb+8+g][...+8]}
// B fragment layout (col-major B 16x8 block, W stored [n][k]):
//  g_Wh[w][((nb*64+kb)*32+lane)] = uint2{b0,b1}
//   b0={W[8nb+g][16kb+tq*2],+1} b1={W[8nb+g][16kb+8+tq*2],+1}
__device__ __align__(16) uint4 g_xp[BB * KK / 8];
__device__ __align__(16) uint4 g_hp[BB * KK / 8];
__device__ __align__(16) uint4 g_rhp[BB * KK / 8];
__device__ __align__(16) float g_Z[BB * HH];
__device__ __align__(16) uint2 g_Wh[6][HH * KK / 4];  // 0:Wwz 1:Wuz 2:Wwr 3:Wur 4:Wu 5:Ww

__device__ __forceinline__ void cp_async16(void* sdst, const void* gsrc) {
    uint32_t s = (uint32_t)__cvta_generic_to_shared(sdst);
    asm volatile("cp.async.cg.shared.global [%0], [%1], 16;\n" :: "r"(s), "l"(gsrc));
}
__device__ __forceinline__ void cp_commit() { asm volatile("cp.async.commit_group;\n"); }
__device__ __forceinline__ void cp_wait_all() { asm volatile("cp.async.wait_group 0;\n"); }

__device__ __forceinline__ void mma16(float c[4], const uint4& a, const uint2& b) {
    asm volatile(
        "mma.sync.aligned.m16n8k16.row.col.f32.f16.f16.f32 "
        "{%0,%1,%2,%3},{%4,%5,%6,%7},{%8,%9},{%0,%1,%2,%3};\n"
        : "+f"(c[0]), "+f"(c[1]), "+f"(c[2]), "+f"(c[3])
        : "r"(a.x), "r"(a.y), "r"(a.z), "r"(a.w), "r"(b.x), "r"(b.y));
}
__device__ __forceinline__ float sig_(float v) { return 1.0f / (1.0f + __expf(-v)); }
__device__ __forceinline__ uint32_t h2u(float a, float b) {
    __half2 h = __floats2half2_rn(a, b);
    return *reinterpret_cast<uint32_t*>(&h);
}

// ---------------------------------------------------------------------------
// Preprocess
// ---------------------------------------------------------------------------
__global__ void __launch_bounds__(256) permA(const float* __restrict__ x,
                                             const float* __restrict__ hm) {
    const float* src = blockIdx.y ? hm : x;
    uint4* dst = blockIdx.y ? g_hp : g_xp;
    int t = blockIdx.x * 256 + threadIdx.x;       // 0..1M-1
    int lane = t & 31, kb = (t >> 5) & 63, rb = t >> 11;
    int g = lane >> 2, tq = lane & 3;
    const float* s = src + (rb * 16 + g) * KK + kb * 16 + tq * 2;
    float2 v00 = *reinterpret_cast<const float2*>(s);
    float2 v10 = *reinterpret_cast<const float2*>(s + 8 * KK);
    float2 v01 = *reinterpret_cast<const float2*>(s + 8);
    float2 v11 = *reinterpret_cast<const float2*>(s + 8 * KK + 8);
    uint4 o;
    o.x = h2u(v00.x, v00.y);
    o.y = h2u(v10.x, v10.y);
    o.z = h2u(v01.x, v01.y);
    o.w = h2u(v11.x, v11.y);
    dst[t] = o;
}

__global__ void __launch_bounds__(256) permB(
    const float* __restrict__ w0, const float* __restrict__ w1,
    const float* __restrict__ w2, const float* __restrict__ w3,
    const float* __restrict__ w4, const float* __restrict__ w5) {
    const float* srcs[6] = {w0, w1, w2, w3, w4, w5};
    const float* src = srcs[blockIdx.y];
    uint2* dst = g_Wh[blockIdx.y];
    int t = blockIdx.x * 256 + threadIdx.x;       // 0..256K-1
    int lane = t & 31, kb = (t >> 5) & 63, nb = t >> 11;
    int g = lane >> 2, tq = lane & 3;
    const float* s = src + (nb * 8 + g) * KK + kb * 16 + tq * 2;
    float2 v0 = *reinterpret_cast<const float2*>(s);
    float2 v1 = *reinterpret_cast<const float2*>(s + 8);
    uint2 o;
    o.x = h2u(v0.x, v0.y);
    o.y = h2u(v1.x, v1.y);
    dst[t] = o;
}

// ---------------------------------------------------------------------------
// Kernel 1: dual-accumulator z/r GEMM. Tile 128x64, BK=64, 8 warps of 32x32.
// smem (uint4 units): A buf*1024 ; Bz 2048+buf*512 ; Br 3072+buf*512  (64KB)
// ---------------------------------------------------------------------------
__global__ void __launch_bounds__(256, 2) gemm_zr(const float* __restrict__ h) {
    extern __shared__ uint4 sm4[];
    const int tid = threadIdx.x, wid = tid >> 5, lane = tid & 31;
    const int g = lane >> 2, tq = lane & 3;
    const int bm = blockIdx.x * 128, bn = blockIdx.y * 64;
    const int rb0 = bm >> 4, nb0 = bn >> 3;

    auto stage = [&](int t, int buf) {
        const int seg = t >> 4, kb = (t & 15) * 4;
        const uint4* Ag = seg ? g_hp : g_xp;
        const uint4* Bz = reinterpret_cast<const uint4*>(g_Wh[seg ? 1 : 0]);
        const uint4* Br = reinterpret_cast<const uint4*>(g_Wh[seg ? 3 : 2]);
        #pragma unroll
        for (int i = 0; i < 4; i++) {
            int c = tid + i * 256, rbl = c >> 7, rem = c & 127;
            cp_async16(&sm4[buf * 1024 + rbl * 128 + rem],
                       &Ag[((rb0 + rbl) * 64 + kb) * 32 + rem]);
        }
        #pragma unroll
        for (int i = 0; i < 2; i++) {
            int c = tid + i * 256, nbl = c >> 6, rem = c & 63;
            int so = ((nb0 + nbl) * 64 + kb) * 16 + rem;
            cp_async16(&sm4[2048 + buf * 512 + nbl * 64 + rem], &Bz[so]);
            cp_async16(&sm4[3072 + buf * 512 + nbl * 64 + rem], &Br[so]);
        }
        cp_commit();
    };

    float accZ[2][4][4] = {}, accR[2][4][4] = {};
    stage(0, 0);

    const int r0 = (wid & 3) * 2, nbl = (wid >> 2) * 4;
    for (int t = 0; t < 32; t++) {
        cp_wait_all();
        __syncthreads();
        if (t + 1 < 32) stage(t + 1, (t + 1) & 1);
        const int buf = t & 1;
        const uint4* A_ = &sm4[buf * 1024];
        const uint2* Bz_ = reinterpret_cast<const uint2*>(&sm4[2048 + buf * 512]);
        const uint2* Br_ = reinterpret_cast<const uint2*>(&sm4[3072 + buf * 512]);
        #pragma unroll
        for (int kk = 0; kk < 4; kk++) {
            uint4 a0 = A_[(r0 * 4 + kk) * 32 + lane];
            uint4 a1 = A_[((r0 + 1) * 4 + kk) * 32 + lane];
            #pragma unroll
            for (int nt = 0; nt < 4; nt++) {
                uint2 bz = Bz_[(nbl + nt) * 128 + kk * 32 + lane];
                uint2 br = Br_[(nbl + nt) * 128 + kk * 32 + lane];
                mma16(accZ[0][nt], a0, bz);
                mma16(accZ[1][nt], a1, bz);
                mma16(accR[0][nt], a0, br);
                mma16(accR[1][nt], a1, br);
            }
        }
        __syncthreads();
    }

    // epilogue: z f32 linear; rh fp16 fragment-ordered
    uint32_t* rhp32 = reinterpret_cast<uint32_t*>(g_rhp);
    const int wm = (wid & 3) * 32, wn = (wid >> 2) * 32;
    #pragma unroll
    for (int mt = 0; mt < 2; mt++) {
        const int rb = ((bm + wm) >> 4) + mt * 1 + ((wm & 16) ? 1 : 0); // wm mult of 32
        const int rbase = bm + wm + mt * 16;
        #pragma unroll
        for (int nt = 0; nt < 4; nt++) {
            const int colb = bn + wn + nt * 8 + tq * 2;
            const int kb = ((bn + wn) >> 4) + (nt >> 1);
            #pragma unroll
            for (int half = 0; half < 2; half++) {
                const int row = rbase + half * 8 + g;
                const int idx = row * HH + colb;
                float2 hv = *reinterpret_cast<const float2*>(&h[idx]);
                float2 zo;
                zo.x = sig_(accZ[mt][nt][half * 2]);
                zo.y = sig_(accZ[mt][nt][half * 2 + 1]);
                *reinterpret_cast<float2*>(&g_Z[idx]) = zo;
                float rh0 = sig_(accR[mt][nt][half * 2]) * hv.x;
                float rh1 = sig_(accR[mt][nt][half * 2 + 1]) * hv.y;
                const int rbm = (rbase >> 4);
                const int regidx = half + 2 * (nt & 1);
                rhp32[(((rbm) * 64 + kb) * 32 + lane) * 4 + regidx] = h2u(rh0, rh1);
            }
        }
    }
}

// ---------------------------------------------------------------------------
// Kernel 2: u = rh Wu^T + x Ww^T ; out = z*h + (1-z)*tanh(u)
// smem (uint4 units): A buf*1024 ; B 2048+buf*512  (48KB)
// ---------------------------------------------------------------------------
__global__ void __launch_bounds__(256, 2) gemm_ht(const float* __restrict__ h,
                                                  float* __restrict__ out) {
    extern __shared__ uint4 sm4[];
    const int tid = threadIdx.x, wid = tid >> 5, lane = tid & 31;
    const int g = lane >> 2, tq = lane & 3;
    const int bm = blockIdx.x * 128, bn = blockIdx.y * 64;
    const int rb0 = bm >> 4, nb0 = bn >> 3;

    auto stage = [&](int t, int buf) {
        const int seg = t >> 4, kb = (t & 15) * 4;
        const uint4* Ag = seg ? g_xp : g_rhp;
        const uint4* Bg = reinterpret_cast<const uint4*>(g_Wh[seg ? 5 : 4]);
        #pragma unroll
        for (int i = 0; i < 4; i++) {
            int c = tid + i * 256, rbl = c >> 7, rem = c & 127;
            cp_async16(&sm4[buf * 1024 + rbl * 128 + rem],
                       &Ag[((rb0 + rbl) * 64 + kb) * 32 + rem]);
        }
        #pragma unroll
        for (int i = 0; i < 2; i++) {
            int c = tid + i * 256, nbl = c >> 6, rem = c & 63;
            cp_async16(&sm4[2048 + buf * 512 + nbl * 64 + rem],
                       &Bg[((nb0 + nbl) * 64 + kb) * 16 + rem]);
        }
        cp_commit();
    };

    float acc[2][4][4] = {};
    stage(0, 0);

    const int r0 = (wid & 3) * 2, nbl = (wid >> 2) * 4;
    for (int t = 0; t < 32; t++) {
        cp_wait_all();
        __syncthreads();
        if (t + 1 < 32) stage(t + 1, (t + 1) & 1);
        const int buf = t & 1;
        const uint4* A_ = &sm4[buf * 1024];
        const uint2* B_ = reinterpret_cast<const uint2*>(&sm4[2048 + buf * 512]);
        #pragma unroll
        for (int kk = 0; kk < 4; kk++) {
            uint4 a0 = A_[(r0 * 4 + kk) * 32 + lane];
            uint4 a1 = A_[((r0 + 1) * 4 + kk) * 32 + lane];
            #pragma unroll
            for (int nt = 0; nt < 4; nt++) {
                uint2 b = B_[(nbl + nt) * 128 + kk * 32 + lane];
                mma16(acc[0][nt], a0, b);
                mma16(acc[1][nt], a1, b);
            }
        }
        __syncthreads();
    }

    const int wm = (wid & 3) * 32, wn = (wid >> 2) * 32;
    #pragma unroll
    for (int mt = 0; mt < 2; mt++) {
        const int rowb = bm + wm + mt * 16 + g;
        #pragma unroll
        for (int nt = 0; nt < 4; nt++) {
            const int colb = bn + wn + nt * 8 + tq * 2;
            #pragma unroll
            for (int half = 0; half < 2; half++) {
                const int idx = (rowb + half * 8) * HH + colb;
                float2 hv = *reinterpret_cast<const float2*>(&h[idx]);
                float2 zv = *reinterpret_cast<const float2*>(&g_Z[idx]);
                float2 ov;
                ov.x = zv.x * hv.x + (1.0f - zv.x) * tanhf(acc[mt][nt][half * 2]);
                ov.y = zv.y * hv.y + (1.0f - zv.y) * tanhf(acc[mt][nt][half * 2 + 1]);
                *reinterpret_cast<float2*>(&out[idx]) = ov;
            }
        }
    }
}

// ---------------------------------------------------------------------------
extern "C" void kernel_launch(void* const* d_in, const int* in_sizes, int n_in,
                              void* d_out, int out_size) {
    const float* x   = (const float*)d_in[0];
    const float* h   = (const float*)d_in[1];
    const float* Wwz = (const float*)d_in[2];
    const float* Wuz = (const float*)d_in[3];
    const float* Wwr = (const float*)d_in[4];
    const float* Wur = (const float*)d_in[5];
    const float* Wu  = (const float*)d_in[6];
    const float* Ww  = (const float*)d_in[7];
    float* out = (float*)d_out;

    const int s1 = 4096 * 16;   // 64 KB
    const int s2 = 3072 * 16;   // 48 KB
    cudaFuncSetAttribute(gemm_zr, cudaFuncAttributeMaxDynamicSharedMemorySize, s1);
    cudaFuncSetAttribute(gemm_ht, cudaFuncAttributeMaxDynamicSharedMemorySize, s2);

    permA<<<dim3(4096, 2), 256>>>(x, h);
    permB<<<dim3(1024, 6), 256>>>(Wwz, Wuz, Wwr, Wur, Wu, Ww);
    gemm_zr<<<dim3(64, 16), 256, s1>>>(h);
    gemm_ht<<<dim3(64, 16), 256, s2>>>(h, out);
}